// round 9
// baseline (speedup 1.0000x reference)
#include <cuda_runtime.h>
#include <cuda_bf16.h>
#include <stdint.h>

// Problem sizes
#define N_TOK   16384
#define E_DIM   256
#define N_E     8192
#define ZQ_ELEMS (N_TOK * E_DIM)
// d_out layout (float32): [ z_q : ZQ_ELEMS ][ loss : 1 ][ idx : N_TOK ]

// GEMM config: C[16384, 8192], K' = 768 (3-term tf32 emulation folded into K)
#define BM 128
#define BN 256
#define NT (N_E / BN)          // 32 n-tiles
#define KP 768                 // 96 k8-blocks
#define NCHUNK 24              // K' staged in 24 chunks of 32
#define TOTAL_GC (NT * NCHUNK) // 768 global chunks

// smem: 2 stages x (A 128x32 + B 256x32) floats = 2 x 12288 floats = 96 KB
#define STAGE_F  12288
#define A_F      4096          // A floats per stage
#define SMEM_DYN (2 * STAGE_F * 4)

// ---------------- scratch ----------------
__device__ float g_zt[N_TOK * E_DIM];            // exact z, [n][c]
__device__ float g_za[96 * N_TOK * 8];           // A' [kb][m][8perm]  48 MB
__device__ float g_eb[96 * N_E * 8];             // B' [kb][n][8perm]  24 MB
__device__ float g_znorm[N_TOK];
__device__ float g_enorm[N_E];
__device__ int   g_idx[N_TOK];
__device__ float g_loss;

// ---------------- helpers ----------------
__device__ __forceinline__ uint32_t smem_to_u32(const void* p) {
    uint32_t a;
    asm("{ .reg .u64 t; cvta.to.shared.u64 t, %1; cvt.u32.u64 %0, t; }" : "=r"(a) : "l"(p));
    return a;
}
__device__ __forceinline__ float tf32_rna(float x) {
    uint32_t u;
    asm("cvt.rna.tf32.f32 %0, %1;" : "=r"(u) : "f"(x));
    return __uint_as_float(u);
}
__device__ __forceinline__ unsigned f2o(float f) {
    unsigned u = __float_as_uint(f);
    return (u & 0x80000000u) ? ~u : (u | 0x80000000u);
}
__device__ __forceinline__ void cpasync16(uint32_t dst, const void* src) {
    asm volatile("cp.async.cg.shared.global [%0], [%1], 16;" :: "r"(dst), "l"(src));
}
#define CP_COMMIT()  asm volatile("cp.async.commit_group;" ::: "memory")
#define CP_WAIT(n)   asm volatile("cp.async.wait_group %0;" :: "n"(n) : "memory")

#define MMA_TF32(d, a0, a1, a2, a3, b0, b1) \
    asm volatile("mma.sync.aligned.m16n8k8.row.col.f32.tf32.tf32.f32 " \
        "{%0,%1,%2,%3}, {%4,%5,%6,%7}, {%8,%9}, {%0,%1,%2,%3};" \
        : "+f"((d)[0]), "+f"((d)[1]), "+f"((d)[2]), "+f"((d)[3]) \
        : "r"(a0), "r"(a1), "r"(a2), "r"(a3), "r"(b0), "r"(b1))

// column permutation for LDS.64 fragment loads: position p holds col perm[p],
// perm = [0,4,1,5,2,6,3,7];  pos(c) = (c&3)*2 + (c>>2)
__device__ __forceinline__ int cpos(int c) { return ((c & 3) << 1) | (c >> 2); }

// ---------------- K1: transpose z + build A' ----------------
// A' regions: kb [0,32): z_hi ; [32,64): z_lo ; [64,96): z_hi
__global__ void transpose_kernel(const float* __restrict__ z) {
    __shared__ float t[32][33];
    int b   = blockIdx.z;
    int c0  = blockIdx.y * 32;
    int hw0 = blockIdx.x * 32;
    int tx = threadIdx.x, ty = threadIdx.y;

    if (blockIdx.x == 0 && blockIdx.y == 0 && blockIdx.z == 0 && tx == 0 && ty == 0)
        g_loss = 0.f;

    #pragma unroll
    for (int i = ty; i < 32; i += 8)
        t[i][tx] = z[((b * 256 + c0 + i) << 10) + hw0 + tx];
    __syncthreads();
    #pragma unroll
    for (int i = ty; i < 32; i += 8) {
        float v = t[tx][i];
        int m = b * 1024 + hw0 + i;
        int k = c0 + tx;
        g_zt[m * 256 + k] = v;
        float hi = tf32_rna(v);
        float lo = tf32_rna(v - hi);
        int kb = k >> 3;
        int base = (kb * N_TOK + m) * 8 + cpos(k & 7);
        g_za[base]                    = hi;   // region 0
        g_za[base + 32 * N_TOK * 8]   = lo;   // region 1
        g_za[base + 64 * N_TOK * 8]   = hi;   // region 2
    }
}

// ---------------- K1c: build B' from emb ----------------
// B' regions: kb [0,32): e_hi ; [32,64): e_hi ; [64,96): e_lo
__global__ void embsplit_kernel(const float* __restrict__ emb) {
    int i = blockIdx.x * blockDim.x + threadIdx.x;   // element over 8192*256
    float v = emb[i];
    int n = i >> 8, k = i & 255;
    float hi = tf32_rna(v);
    float lo = tf32_rna(v - hi);
    int kb = k >> 3;
    int base = (kb * N_E + n) * 8 + cpos(k & 7);
    g_eb[base]                  = hi;
    g_eb[base + 32 * N_E * 8]   = hi;
    g_eb[base + 64 * N_E * 8]   = lo;
}

// ---------------- K1b: exact fp32 row norms ----------------
__global__ void norms_kernel(const float* __restrict__ emb) {
    int gw   = (blockIdx.x * blockDim.x + threadIdx.x) >> 5;
    int lane = threadIdx.x & 31;
    const float* src;
    float* dst;
    if (gw < N_TOK)            { src = g_zt + gw * 256;           dst = g_znorm + gw; }
    else if (gw < N_TOK + N_E) { src = emb  + (gw - N_TOK) * 256; dst = g_enorm + (gw - N_TOK); }
    else return;

    const float4* p = (const float4*)src;
    float s = 0.f;
    #pragma unroll
    for (int i = 0; i < 2; i++) {
        float4 v = p[lane + 32 * i];
        s = fmaf(v.x, v.x, s); s = fmaf(v.y, v.y, s);
        s = fmaf(v.z, v.z, s); s = fmaf(v.w, v.w, s);
    }
    #pragma unroll
    for (int o = 16; o; o >>= 1) s += __shfl_xor_sync(0xFFFFFFFFu, s, o);
    if (lane == 0) *dst = s;
}

// ---------------- K2: mma.sync tf32 GEMM + fused argmin ----------------
// 128 CTAs, 512 threads: 16 warps as 2m x 8n, warp tile 64x32.
__global__ void __launch_bounds__(512, 1) vq_mma_kernel(float* __restrict__ out_idx_f) {
    extern __shared__ float sm[];
    const uint32_t smb = smem_to_u32(sm);

    const int tid = threadIdx.x, wid = tid >> 5, lane = tid & 31;
    const int g = lane >> 2, tig = lane & 3;
    const int wm = wid >> 3, wn = wid & 7;     // 2 x 8 warp grid
    const int m0 = blockIdx.x * BM;

    // preload zn for the 8 rows this thread owns
    float zn[4][2];
    #pragma unroll
    for (int t = 0; t < 4; t++) {
        zn[t][0] = g_znorm[m0 + wm * 64 + t * 16 + g];
        zn[t][1] = g_znorm[m0 + wm * 64 + t * 16 + g + 8];
    }

    float best[8];
    int   bidx[8];
    #pragma unroll
    for (int i = 0; i < 8; i++) { best[i] = __int_as_float(0x7F800000); bidx[i] = 0; }

    float acc[4][4][4];   // [mt][nt][frag] -- warp tile 64x32

    // stage loader: global chunk gc -> stage gc&1 (512 threads)
    auto issue = [&](int gc) {
        int nt = gc / NCHUNK, c = gc % NCHUNK, s = gc & 1;
        int n0 = nt * BN;
        uint32_t ab = smb + (uint32_t)s * (STAGE_F * 4);
        // A: 4 k8-blocks x 1024 floats = 1024 x 16B ops
        #pragma unroll
        for (int i = 0; i < 2; i++) {
            int o = tid + 512 * i, j = o >> 8, u = o & 255;
            const float* src = g_za + ((size_t)(4 * c + j) * N_TOK + m0) * 8 + u * 4;
            cpasync16(ab + j * 4096 + u * 16, src);
        }
        // B: 4 k8-blocks x 2048 floats = 2048 x 16B ops
        uint32_t bb = ab + A_F * 4;
        #pragma unroll
        for (int i = 0; i < 4; i++) {
            int o = tid + 512 * i, j = o >> 9, u = o & 511;
            const float* src = g_eb + ((size_t)(4 * c + j) * N_E + n0) * 8 + u * 4;
            cpasync16(bb + j * 8192 + u * 16, src);
        }
        CP_COMMIT();
    };

    issue(0);

    for (int nt = 0; nt < NT; nt++) {
        #pragma unroll
        for (int t = 0; t < 4; t++)
            #pragma unroll
            for (int tn = 0; tn < 4; tn++)
                #pragma unroll
                for (int r = 0; r < 4; r++) acc[t][tn][r] = 0.f;

        for (int c = 0; c < NCHUNK; c++) {
            int gc = nt * NCHUNK + c;
            if (gc + 1 < TOTAL_GC) { issue(gc + 1); CP_WAIT(1); }
            else                   { CP_WAIT(0); }
            __syncthreads();

            const int Sf = (gc & 1) * STAGE_F;
            #pragma unroll
            for (int b = 0; b < 4; b++) {
                uint32_t ar[4][4];
                #pragma unroll
                for (int t = 0; t < 4; t++) {
                    int ro = Sf + b * 1024 + (wm * 64 + t * 16 + g) * 8 + tig * 2;
                    float2 v0 = *(const float2*)&sm[ro];
                    float2 v1 = *(const float2*)&sm[ro + 64];
                    ar[t][0] = __float_as_uint(v0.x); ar[t][2] = __float_as_uint(v0.y);
                    ar[t][1] = __float_as_uint(v1.x); ar[t][3] = __float_as_uint(v1.y);
                }
                uint32_t br[4][2];
                #pragma unroll
                for (int tn = 0; tn < 4; tn++) {
                    int bo = Sf + A_F + b * 2048 + (wn * 32 + tn * 8 + g) * 8 + tig * 2;
                    float2 v = *(const float2*)&sm[bo];
                    br[tn][0] = __float_as_uint(v.x); br[tn][1] = __float_as_uint(v.y);
                }
                #pragma unroll
                for (int t = 0; t < 4; t++)
                    #pragma unroll
                    for (int tn = 0; tn < 4; tn++)
                        MMA_TF32(acc[t][tn], ar[t][0], ar[t][1], ar[t][2], ar[t][3],
                                 br[tn][0], br[tn][1]);
            }
            __syncthreads();
        }

        // per-tile argmin fold (registers only; no smem touched)
        int n0 = nt * BN;
        #pragma unroll
        for (int t = 0; t < 4; t++) {
            #pragma unroll
            for (int tn = 0; tn < 4; tn++) {
                int cb = n0 + wn * 32 + tn * 8 + 2 * tig;
                float en0 = __ldg(&g_enorm[cb]);
                float en1 = __ldg(&g_enorm[cb + 1]);
                float s00 = fmaf(-2.f, acc[t][tn][0], zn[t][0] + en0);
                float s01 = fmaf(-2.f, acc[t][tn][1], zn[t][0] + en1);
                float s10 = fmaf(-2.f, acc[t][tn][2], zn[t][1] + en0);
                float s11 = fmaf(-2.f, acc[t][tn][3], zn[t][1] + en1);
                int s0 = t * 2, s1 = t * 2 + 1;
                if (s00 < best[s0]) { best[s0] = s00; bidx[s0] = cb; }
                if (s01 < best[s0]) { best[s0] = s01; bidx[s0] = cb + 1; }
                if (s10 < best[s1]) { best[s1] = s10; bidx[s1] = cb; }
                if (s11 < best[s1]) { best[s1] = s11; bidx[s1] = cb + 1; }
            }
        }
    }

    // merge across threads via packed (score,idx) atomicMin in smem
    __syncthreads();
    unsigned long long* sKey = (unsigned long long*)sm;
    if (tid < BM) sKey[tid] = 0xFFFFFFFFFFFFFFFFull;
    __syncthreads();
    #pragma unroll
    for (int slot = 0; slot < 8; slot++) {
        int t = slot >> 1, which = slot & 1;
        int rl = wm * 64 + t * 16 + g + which * 8;
        unsigned long long key =
            ((unsigned long long)f2o(best[slot]) << 32) | (unsigned)bidx[slot];
        atomicMin(&sKey[rl], key);
    }
    __syncthreads();
    if (tid < BM) {
        int idx = (int)(unsigned)(sKey[tid] & 0xFFFFFFFFull);
        g_idx[m0 + tid] = idx;
        out_idx_f[m0 + tid] = (float)idx;
    }
}

// ---------------- K3: gather z_q (straight-through rounding) + loss ------
__global__ void epilogue_kernel(const float* __restrict__ emb, float* __restrict__ out) {
    int bh = blockIdx.x;
    int b = bh >> 5, h = bh & 31;
    int w    = threadIdx.x >> 5;
    int lane = threadIdx.x & 31;
    int n = (b << 10) + (h << 5) + w;
    int idx = g_idx[n];

    const float4* ep = (const float4*)(emb  + idx * 256);
    const float4* zp = (const float4*)(g_zt + n   * 256);
    float ls = 0.f;
    #pragma unroll
    for (int i = 0; i < 2; i++) {
        float4 e  = ep[lane + 32 * i];
        float4 zv = zp[lane + 32 * i];
        int c = (lane + 32 * i) * 4;
        int base = (b * 256 + c) * 1024 + h * 32 + w;
        // match reference straight-through: zt + (z_q - zt), two fp32 roundings
        out[base]        = __fadd_rn(zv.x, __fsub_rn(e.x, zv.x));
        out[base + 1024] = __fadd_rn(zv.y, __fsub_rn(e.y, zv.y));
        out[base + 2048] = __fadd_rn(zv.z, __fsub_rn(e.z, zv.z));
        out[base + 3072] = __fadd_rn(zv.w, __fsub_rn(e.w, zv.w));
        float dx = e.x - zv.x, dy = e.y - zv.y, dz = e.z - zv.z, dw = e.w - zv.w;
        ls += dx * dx + dy * dy + dz * dz + dw * dw;
    }
    #pragma unroll
    for (int o = 16; o; o >>= 1) ls += __shfl_xor_sync(0xFFFFFFFFu, ls, o);
    __shared__ float red[32];
    if (lane == 0) red[w] = ls;
    __syncthreads();
    if (threadIdx.x < 32) {
        float v = red[threadIdx.x];
        #pragma unroll
        for (int o = 16; o; o >>= 1) v += __shfl_xor_sync(0xFFFFFFFFu, v, o);
        if (threadIdx.x == 0) atomicAdd(&g_loss, v);
    }
}

__global__ void finalize_kernel(float* __restrict__ out_loss) {
    out_loss[0] = 1.25f * g_loss * (1.0f / (float)ZQ_ELEMS);
}

// ---------------- launch ----------------
extern "C" void kernel_launch(void* const* d_in, const int* in_sizes, int n_in,
                              void* d_out, int out_size) {
    const float* z   = (const float*)d_in[0];
    const float* emb = (const float*)d_in[1];
    float* out = (float*)d_out;

    cudaFuncSetAttribute(vq_mma_kernel, cudaFuncAttributeMaxDynamicSharedMemorySize, SMEM_DYN);

    transpose_kernel<<<dim3(32, 8, 16), dim3(32, 8)>>>(z);
    embsplit_kernel<<<(N_E * E_DIM) / 256, 256>>>(emb);
    norms_kernel<<<(N_TOK + N_E) / 8, 256>>>(emb);
    vq_mma_kernel<<<N_TOK / BM, 512, SMEM_DYN>>>(out + ZQ_ELEMS + 1);
    epilogue_kernel<<<512, 1024>>>(emb, out);
    finalize_kernel<<<1, 1>>>(out + ZQ_ELEMS);
}

// round 10
// speedup vs baseline: 1.8920x; 1.8920x over previous
#include <cuda_runtime.h>
#include <cuda_fp16.h>
#include <stdint.h>

// Problem sizes
#define N_TOK   16384
#define E_DIM   256
#define N_E     8192
#define ZQ_ELEMS (N_TOK * E_DIM)
// d_out layout (float32): [ z_q : ZQ_ELEMS ][ loss : 1 ][ idx : N_TOK ]

// GEMM config: C[16384, 8192], K' = 768 fp16 (3-term hi/lo emulation in K)
// B (codebook) pre-scaled by 2^12 so both fp16 halves are normal numbers.
#define BM 128
#define BN 256
#define NT (N_E / BN)          // 32 n-tiles
#define NCHUNK 24              // K' = 768 staged in 24 chunks of 32 (= 2 k16 blocks)
#define TOTAL_GC (NT * NCHUNK) // 768 global chunks
#define KB16 48                // total k16 blocks (3 regions x 16)

// smem: 4 stages x (A 128x32 + B 256x32 fp16) = 4 x 24KB = 96KB
#define STAGE_B  24576
#define SMEM_DYN (4 * STAGE_B)

// ---------------- scratch ----------------
__device__ float  g_zt[N_TOK * E_DIM];          // exact z, [n][c]
__device__ __half g_za[(size_t)KB16 * N_TOK * 16];  // A' [kb][m][16perm]  25 MB
__device__ __half g_eb[(size_t)KB16 * N_E  * 16];   // B' [kb][n][16perm]  12.6 MB
__device__ float  g_znorm[N_TOK];
__device__ float  g_enorm[N_E];
__device__ int    g_idx[N_TOK];
__device__ float  g_loss;

// ---------------- helpers ----------------
__device__ __forceinline__ uint32_t smem_to_u32(const void* p) {
    uint32_t a;
    asm("{ .reg .u64 t; cvta.to.shared.u64 t, %1; cvt.u32.u64 %0, t; }" : "=r"(a) : "l"(p));
    return a;
}
__device__ __forceinline__ unsigned f2o(float f) {
    unsigned u = __float_as_uint(f);
    return (u & 0x80000000u) ? ~u : (u | 0x80000000u);
}
__device__ __forceinline__ void cpasync16(uint32_t dst, const void* src) {
    asm volatile("cp.async.cg.shared.global [%0], [%1], 16;" :: "r"(dst), "l"(src));
}
#define CP_COMMIT()  asm volatile("cp.async.commit_group;" ::: "memory")
#define CP_WAIT(n)   asm volatile("cp.async.wait_group %0;" :: "n"(n) : "memory")

#define MMA_FP16(d, a0, a1, a2, a3, b0, b1) \
    asm volatile("mma.sync.aligned.m16n8k16.row.col.f32.f16.f16.f32 " \
        "{%0,%1,%2,%3}, {%4,%5,%6,%7}, {%8,%9}, {%0,%1,%2,%3};" \
        : "+f"((d)[0]), "+f"((d)[1]), "+f"((d)[2]), "+f"((d)[3]) \
        : "r"(a0), "r"(a1), "r"(a2), "r"(a3), "r"(b0), "r"(b1))

// fp16 k16 fragment permutation: thread tig reads 8B at [row][tig*8] getting
// k = {2t, 2t+1, 2t+8, 2t+9}.  pos(k) = ((k&7)>>1)*4 + ((k>>3)&1)*2 + (k&1)
__device__ __forceinline__ int pos16(int k) {
    return (((k & 7) >> 1) << 2) | (((k >> 3) & 1) << 1) | (k & 1);
}

// ---------------- K1: transpose z + build A' (fp16 hi/lo) ----------------
// A' regions (k16 blocks): [0,16): z_hi ; [16,32): z_lo ; [32,48): z_hi
__global__ void transpose_kernel(const float* __restrict__ z) {
    __shared__ float t[32][33];
    int b   = blockIdx.z;
    int c0  = blockIdx.y * 32;
    int hw0 = blockIdx.x * 32;
    int tx = threadIdx.x, ty = threadIdx.y;

    if (blockIdx.x == 0 && blockIdx.y == 0 && blockIdx.z == 0 && tx == 0 && ty == 0)
        g_loss = 0.f;

    #pragma unroll
    for (int i = ty; i < 32; i += 8)
        t[i][tx] = z[((b * 256 + c0 + i) << 10) + hw0 + tx];
    __syncthreads();
    const size_t RS = (size_t)16 * N_TOK * 16;   // region stride (elements)
    #pragma unroll
    for (int i = ty; i < 32; i += 8) {
        float v = t[tx][i];
        int m = b * 1024 + hw0 + i;
        int k = c0 + tx;
        g_zt[m * 256 + k] = v;
        __half hi = __float2half_rn(v);
        __half lo = __float2half_rn(v - __half2float(hi));
        size_t base = ((size_t)(k >> 4) * N_TOK + m) * 16 + pos16(k & 15);
        g_za[base]          = hi;   // region 0 (pairs with e_hi)
        g_za[base + RS]     = lo;   // region 1 (pairs with e_hi)
        g_za[base + 2 * RS] = hi;   // region 2 (pairs with e_lo)
    }
}

// ---------------- K1c: build B' from emb (scaled by 2^12, fp16 hi/lo) ----
// B' regions: [0,16): e_hi ; [16,32): e_hi ; [32,48): e_lo
__global__ void embsplit_kernel(const float* __restrict__ emb) {
    int i = blockIdx.x * blockDim.x + threadIdx.x;   // element over 8192*256
    float v = emb[i] * 4096.0f;                      // exact (power of 2)
    int n = i >> 8, k = i & 255;
    __half hi = __float2half_rn(v);
    __half lo = __float2half_rn(v - __half2float(hi));
    const size_t RS = (size_t)16 * N_E * 16;
    size_t base = ((size_t)(k >> 4) * N_E + n) * 16 + pos16(k & 15);
    g_eb[base]          = hi;
    g_eb[base + RS]     = hi;
    g_eb[base + 2 * RS] = lo;
}

// ---------------- K1b: exact fp32 row norms ----------------
__global__ void norms_kernel(const float* __restrict__ emb) {
    int gw   = (blockIdx.x * blockDim.x + threadIdx.x) >> 5;
    int lane = threadIdx.x & 31;
    const float* src;
    float* dst;
    if (gw < N_TOK)            { src = g_zt + gw * 256;           dst = g_znorm + gw; }
    else if (gw < N_TOK + N_E) { src = emb  + (gw - N_TOK) * 256; dst = g_enorm + (gw - N_TOK); }
    else return;

    const float4* p = (const float4*)src;
    float s = 0.f;
    #pragma unroll
    for (int i = 0; i < 2; i++) {
        float4 v = p[lane + 32 * i];
        s = fmaf(v.x, v.x, s); s = fmaf(v.y, v.y, s);
        s = fmaf(v.z, v.z, s); s = fmaf(v.w, v.w, s);
    }
    #pragma unroll
    for (int o = 16; o; o >>= 1) s += __shfl_xor_sync(0xFFFFFFFFu, s, o);
    if (lane == 0) *dst = s;
}

// ---------------- K2: mma.sync fp16 GEMM + fused argmin ----------------
// 128 CTAs, 256 threads: 8 warps as 2m x 4n, warp tile 64x64, 4-stage ring.
__global__ void __launch_bounds__(256, 1) vq_mma_kernel(float* __restrict__ out_idx_f) {
    extern __shared__ char smc[];
    const uint32_t smb = smem_to_u32(smc);

    const int tid = threadIdx.x, wid = tid >> 5, lane = tid & 31;
    const int g = lane >> 2, tig = lane & 3;
    const int wm = wid >> 2, wn = wid & 3;     // 2 x 4 warp grid
    const int m0 = blockIdx.x * BM;

    float zn[4][2];
    #pragma unroll
    for (int t = 0; t < 4; t++) {
        zn[t][0] = g_znorm[m0 + wm * 64 + t * 16 + g];
        zn[t][1] = g_znorm[m0 + wm * 64 + t * 16 + g + 8];
    }

    float best[8];
    int   bidx[8];
    #pragma unroll
    for (int i = 0; i < 8; i++) { best[i] = __int_as_float(0x7F800000); bidx[i] = 0; }

    float acc[4][8][4];   // [mt][nt][frag] -- warp tile 64x64, n8 per frag

    // stage loader: global chunk gc (32 k = 2 k16-blocks) -> stage gc&3
    auto issue = [&](int gc) {
        int nt = gc / NCHUNK, c = gc % NCHUNK, s = gc & 3;
        int n0 = nt * BN;
        uint32_t sb = smb + (uint32_t)s * STAGE_B;
        // A: 2 kb x 128 rows x 32B = 8KB -> 512 x 16B, 2 per thread
        #pragma unroll
        for (int i = 0; i < 2; i++) {
            int o = tid + 256 * i, j = o >> 8, u = o & 255;
            const __half* src = g_za + ((size_t)(2 * c + j) * N_TOK + m0) * 16 + u * 8;
            cpasync16(sb + j * 4096 + u * 16, src);
        }
        // B: 2 kb x 256 rows x 32B = 16KB -> 1024 x 16B, 4 per thread
        #pragma unroll
        for (int i = 0; i < 4; i++) {
            int o = tid + 256 * i, j = o >> 9, u = o & 511;
            const __half* src = g_eb + ((size_t)(2 * c + j) * N_E + n0) * 16 + u * 8;
            cpasync16(sb + 8192 + j * 8192 + u * 16, src);
        }
        CP_COMMIT();
    };

    issue(0); issue(1); issue(2);

    for (int nt = 0; nt < NT; nt++) {
        #pragma unroll
        for (int t = 0; t < 4; t++)
            #pragma unroll
            for (int tn = 0; tn < 8; tn++)
                #pragma unroll
                for (int r = 0; r < 4; r++) acc[t][tn][r] = 0.f;

        for (int c = 0; c < NCHUNK; c++) {
            int gc = nt * NCHUNK + c;
            if (gc + 3 < TOTAL_GC) { issue(gc + 3); CP_WAIT(3); }
            else {
                int rem = TOTAL_GC - 1 - gc;
                if (rem >= 3)      CP_WAIT(3);
                else if (rem == 2) CP_WAIT(2);
                else if (rem == 1) CP_WAIT(1);
                else               CP_WAIT(0);
            }
            __syncthreads();

            const uint32_t Sb = (uint32_t)(gc & 3) * STAGE_B;
            #pragma unroll
            for (int b = 0; b < 2; b++) {
                uint32_t ar[4][4];
                #pragma unroll
                for (int t = 0; t < 4; t++) {
                    const char* ra = smc + Sb + b * 4096
                                   + (wm * 64 + t * 16 + g) * 32 + tig * 8;
                    uint2 v0 = *(const uint2*)ra;          // row g   : a0, a2
                    uint2 v1 = *(const uint2*)(ra + 256);  // row g+8 : a1, a3
                    ar[t][0] = v0.x; ar[t][2] = v0.y;
                    ar[t][1] = v1.x; ar[t][3] = v1.y;
                }
                uint32_t br[8][2];
                #pragma unroll
                for (int tn = 0; tn < 8; tn++) {
                    const char* rb = smc + Sb + 8192 + b * 8192
                                   + (wn * 64 + tn * 8 + g) * 32 + tig * 8;
                    uint2 v = *(const uint2*)rb;
                    br[tn][0] = v.x; br[tn][1] = v.y;
                }
                #pragma unroll
                for (int t = 0; t < 4; t++)
                    #pragma unroll
                    for (int tn = 0; tn < 8; tn++)
                        MMA_FP16(acc[t][tn], ar[t][0], ar[t][1], ar[t][2], ar[t][3],
                                 br[tn][0], br[tn][1]);
            }
            __syncthreads();
        }

        // per-tile argmin fold; dot = acc * 2^-12, so s = fmaf(-2^-11, acc, zn+en)
        int n0 = nt * BN;
        #pragma unroll
        for (int t = 0; t < 4; t++) {
            #pragma unroll
            for (int tn = 0; tn < 8; tn++) {
                int cb = n0 + wn * 64 + tn * 8 + 2 * tig;
                float en0 = __ldg(&g_enorm[cb]);
                float en1 = __ldg(&g_enorm[cb + 1]);
                const float SC = -4.8828125e-4f;   // -2^-11, exact
                float s00 = fmaf(SC, acc[t][tn][0], zn[t][0] + en0);
                float s01 = fmaf(SC, acc[t][tn][1], zn[t][0] + en1);
                float s10 = fmaf(SC, acc[t][tn][2], zn[t][1] + en0);
                float s11 = fmaf(SC, acc[t][tn][3], zn[t][1] + en1);
                int s0 = t * 2, s1 = t * 2 + 1;
                if (s00 < best[s0]) { best[s0] = s00; bidx[s0] = cb; }
                if (s01 < best[s0]) { best[s0] = s01; bidx[s0] = cb + 1; }
                if (s10 < best[s1]) { best[s1] = s10; bidx[s1] = cb; }
                if (s11 < best[s1]) { best[s1] = s11; bidx[s1] = cb + 1; }
            }
        }
    }

    // merge across threads via packed (score,idx) atomicMin in smem
    __syncthreads();
    unsigned long long* sKey = (unsigned long long*)smc;
    if (tid < BM) sKey[tid] = 0xFFFFFFFFFFFFFFFFull;
    __syncthreads();
    #pragma unroll
    for (int slot = 0; slot < 8; slot++) {
        int t = slot >> 1, which = slot & 1;
        int rl = wm * 64 + t * 16 + g + which * 8;
        unsigned long long key =
            ((unsigned long long)f2o(best[slot]) << 32) | (unsigned)bidx[slot];
        atomicMin(&sKey[rl], key);
    }
    __syncthreads();
    if (tid < BM) {
        int idx = (int)(unsigned)(sKey[tid] & 0xFFFFFFFFull);
        g_idx[m0 + tid] = idx;
        out_idx_f[m0 + tid] = (float)idx;
    }
}

// ---------------- K3: gather z_q (straight-through rounding) + loss ------
__global__ void epilogue_kernel(const float* __restrict__ emb, float* __restrict__ out) {
    int bh = blockIdx.x;
    int b = bh >> 5, h = bh & 31;
    int w    = threadIdx.x >> 5;
    int lane = threadIdx.x & 31;
    int n = (b << 10) + (h << 5) + w;
    int idx = g_idx[n];

    const float4* ep = (const float4*)(emb  + idx * 256);
    const float4* zp = (const float4*)(g_zt + n   * 256);
    float ls = 0.f;
    #pragma unroll
    for (int i = 0; i < 2; i++) {
        float4 e  = ep[lane + 32 * i];
        float4 zv = zp[lane + 32 * i];
        int c = (lane + 32 * i) * 4;
        int base = (b * 256 + c) * 1024 + h * 32 + w;
        out[base]        = __fadd_rn(zv.x, __fsub_rn(e.x, zv.x));
        out[base + 1024] = __fadd_rn(zv.y, __fsub_rn(e.y, zv.y));
        out[base + 2048] = __fadd_rn(zv.z, __fsub_rn(e.z, zv.z));
        out[base + 3072] = __fadd_rn(zv.w, __fsub_rn(e.w, zv.w));
        float dx = e.x - zv.x, dy = e.y - zv.y, dz = e.z - zv.z, dw = e.w - zv.w;
        ls += dx * dx + dy * dy + dz * dz + dw * dw;
    }
    #pragma unroll
    for (int o = 16; o; o >>= 1) ls += __shfl_xor_sync(0xFFFFFFFFu, ls, o);
    __shared__ float red[32];
    if (lane == 0) red[w] = ls;
    __syncthreads();
    if (threadIdx.x < 32) {
        float v = red[threadIdx.x];
        #pragma unroll
        for (int o = 16; o; o >>= 1) v += __shfl_xor_sync(0xFFFFFFFFu, v, o);
        if (threadIdx.x == 0) atomicAdd(&g_loss, v);
    }
}

__global__ void finalize_kernel(float* __restrict__ out_loss) {
    out_loss[0] = 1.25f * g_loss * (1.0f / (float)ZQ_ELEMS);
}

// ---------------- launch ----------------
extern "C" void kernel_launch(void* const* d_in, const int* in_sizes, int n_in,
                              void* d_out, int out_size) {
    const float* z   = (const float*)d_in[0];
    const float* emb = (const float*)d_in[1];
    float* out = (float*)d_out;

    cudaFuncSetAttribute(vq_mma_kernel, cudaFuncAttributeMaxDynamicSharedMemorySize, SMEM_DYN);

    transpose_kernel<<<dim3(32, 8, 16), dim3(32, 8)>>>(z);
    embsplit_kernel<<<(N_E * E_DIM) / 256, 256>>>(emb);
    norms_kernel<<<(N_TOK + N_E) / 8, 256>>>(emb);
    vq_mma_kernel<<<N_TOK / BM, 256, SMEM_DYN>>>(out + ZQ_ELEMS + 1);
    epilogue_kernel<<<512, 1024>>>(emb, out);
    finalize_kernel<<<1, 1>>>(out + ZQ_ELEMS);
}

// round 11
// speedup vs baseline: 1.9385x; 1.0246x over previous
#include <cuda_runtime.h>
#include <cuda_fp16.h>
#include <stdint.h>

// Problem sizes
#define N_TOK   16384
#define E_DIM   256
#define N_E     8192
#define ZQ_ELEMS (N_TOK * E_DIM)
// d_out layout (float32): [ z_q : ZQ_ELEMS ][ loss : 1 ][ idx : N_TOK ]

// GEMM config: C[16384, 8192], K' = 768 fp16 (3-term hi/lo emulation in K)
// B (codebook) pre-scaled by 2^12 so both fp16 halves are normal numbers.
#define BM 128
#define BN 256
#define NT (N_E / BN)          // 32 n-tiles
#define NCHUNK 24              // K' = 768 staged in 24 chunks of 32 (= 2 k16 blocks)
#define PAIRS  12              // chunks processed in pairs (one sync per pair)
#define TOTAL_PR (NT * PAIRS)  // 384 global pairs
#define KB16 48                // total k16 blocks (3 regions x 16)

// smem: 4 stages x (A 128x32 + B 256x32 fp16) = 4 x 24KB = 96KB
#define STAGE_B  24576
#define SMEM_DYN (4 * STAGE_B)

// ---------------- scratch ----------------
__device__ float  g_zt[N_TOK * E_DIM];          // exact z, [n][c]
__device__ __half g_za[(size_t)KB16 * N_TOK * 16];  // A' [kb][m][16perm]  25 MB
__device__ __half g_eb[(size_t)KB16 * N_E  * 16];   // B' [kb][n][16perm]  12.6 MB
__device__ float  g_znorm[N_TOK];
__device__ float  g_enorm[N_E];
__device__ int    g_idx[N_TOK];
__device__ float  g_loss;

// ---------------- helpers ----------------
__device__ __forceinline__ uint32_t smem_to_u32(const void* p) {
    uint32_t a;
    asm("{ .reg .u64 t; cvta.to.shared.u64 t, %1; cvt.u32.u64 %0, t; }" : "=r"(a) : "l"(p));
    return a;
}
__device__ __forceinline__ unsigned f2o(float f) {
    unsigned u = __float_as_uint(f);
    return (u & 0x80000000u) ? ~u : (u | 0x80000000u);
}
__device__ __forceinline__ void cpasync16(uint32_t dst, const void* src) {
    asm volatile("cp.async.cg.shared.global [%0], [%1], 16;" :: "r"(dst), "l"(src));
}
#define CP_COMMIT()  asm volatile("cp.async.commit_group;" ::: "memory")
#define CP_WAIT(n)   asm volatile("cp.async.wait_group %0;" :: "n"(n) : "memory")

#define MMA_FP16(d, a0, a1, a2, a3, b0, b1) \
    asm volatile("mma.sync.aligned.m16n8k16.row.col.f32.f16.f16.f32 " \
        "{%0,%1,%2,%3}, {%4,%5,%6,%7}, {%8,%9}, {%0,%1,%2,%3};" \
        : "+f"((d)[0]), "+f"((d)[1]), "+f"((d)[2]), "+f"((d)[3]) \
        : "r"(a0), "r"(a1), "r"(a2), "r"(a3), "r"(b0), "r"(b1))

// fp16 k16 fragment permutation: thread tig reads 8B at [row][tig*8] getting
// k = {2t, 2t+1, 2t+8, 2t+9}.  pos(k) = ((k&7)>>1)*4 + ((k>>3)&1)*2 + (k&1)
__device__ __forceinline__ int pos16(int k) {
    return (((k & 7) >> 1) << 2) | (((k >> 3) & 1) << 1) | (k & 1);
}

// ---------------- K1: transpose z + build A' (fp16 hi/lo) ----------------
// A' regions (k16 blocks): [0,16): z_hi ; [16,32): z_lo ; [32,48): z_hi
__global__ void transpose_kernel(const float* __restrict__ z) {
    __shared__ float t[32][33];
    int b   = blockIdx.z;
    int c0  = blockIdx.y * 32;
    int hw0 = blockIdx.x * 32;
    int tx = threadIdx.x, ty = threadIdx.y;

    if (blockIdx.x == 0 && blockIdx.y == 0 && blockIdx.z == 0 && tx == 0 && ty == 0)
        g_loss = 0.f;

    #pragma unroll
    for (int i = ty; i < 32; i += 8)
        t[i][tx] = z[((b * 256 + c0 + i) << 10) + hw0 + tx];
    __syncthreads();
    const size_t RS = (size_t)16 * N_TOK * 16;   // region stride (elements)
    #pragma unroll
    for (int i = ty; i < 32; i += 8) {
        float v = t[tx][i];
        int m = b * 1024 + hw0 + i;
        int k = c0 + tx;
        g_zt[m * 256 + k] = v;
        __half hi = __float2half_rn(v);
        __half lo = __float2half_rn(v - __half2float(hi));
        size_t base = ((size_t)(k >> 4) * N_TOK + m) * 16 + pos16(k & 15);
        g_za[base]          = hi;   // region 0 (pairs with e_hi)
        g_za[base + RS]     = lo;   // region 1 (pairs with e_hi)
        g_za[base + 2 * RS] = hi;   // region 2 (pairs with e_lo)
    }
}

// ---------------- K1c: build B' from emb (scaled by 2^12, fp16 hi/lo) ----
// B' regions: [0,16): e_hi ; [16,32): e_hi ; [32,48): e_lo
__global__ void embsplit_kernel(const float* __restrict__ emb) {
    int i = blockIdx.x * blockDim.x + threadIdx.x;   // element over 8192*256
    float v = emb[i] * 4096.0f;                      // exact (power of 2)
    int n = i >> 8, k = i & 255;
    __half hi = __float2half_rn(v);
    __half lo = __float2half_rn(v - __half2float(hi));
    const size_t RS = (size_t)16 * N_E * 16;
    size_t base = ((size_t)(k >> 4) * N_E + n) * 16 + pos16(k & 15);
    g_eb[base]          = hi;
    g_eb[base + RS]     = hi;
    g_eb[base + 2 * RS] = lo;
}

// ---------------- K1b: exact fp32 row norms ----------------
__global__ void norms_kernel(const float* __restrict__ emb) {
    int gw   = (blockIdx.x * blockDim.x + threadIdx.x) >> 5;
    int lane = threadIdx.x & 31;
    const float* src;
    float* dst;
    if (gw < N_TOK)            { src = g_zt + gw * 256;           dst = g_znorm + gw; }
    else if (gw < N_TOK + N_E) { src = emb  + (gw - N_TOK) * 256; dst = g_enorm + (gw - N_TOK); }
    else return;

    const float4* p = (const float4*)src;
    float s = 0.f;
    #pragma unroll
    for (int i = 0; i < 2; i++) {
        float4 v = p[lane + 32 * i];
        s = fmaf(v.x, v.x, s); s = fmaf(v.y, v.y, s);
        s = fmaf(v.z, v.z, s); s = fmaf(v.w, v.w, s);
    }
    #pragma unroll
    for (int o = 16; o; o >>= 1) s += __shfl_xor_sync(0xFFFFFFFFu, s, o);
    if (lane == 0) *dst = s;
}

// ---------------- K2: mma.sync fp16 GEMM + fused argmin ----------------
// 128 CTAs, 256 threads: 8 warps as 2m x 4n, warp tile 64x64.
// Chunks processed in PAIRS: one __syncthreads per pair, cp.async issued for
// pair gp+1 right after sync(gp) (targets stage-set read in pair gp-1, which
// the sync proves drained). Register double-buffered fragments overlap the
// smem crossbar with the tensor pipe inside each warp.
__global__ void __launch_bounds__(256, 1) vq_mma_kernel(float* __restrict__ out_idx_f) {
    extern __shared__ char smc[];
    const uint32_t smb = smem_to_u32(smc);

    const int tid = threadIdx.x, wid = tid >> 5, lane = tid & 31;
    const int g = lane >> 2, tig = lane & 3;
    const int wm = wid >> 2, wn = wid & 3;     // 2 x 4 warp grid
    const int m0 = blockIdx.x * BM;

    float zn[4][2];
    #pragma unroll
    for (int t = 0; t < 4; t++) {
        zn[t][0] = g_znorm[m0 + wm * 64 + t * 16 + g];
        zn[t][1] = g_znorm[m0 + wm * 64 + t * 16 + g + 8];
    }

    float best[8];
    int   bidx[8];
    #pragma unroll
    for (int i = 0; i < 8; i++) { best[i] = __int_as_float(0x7F800000); bidx[i] = 0; }

    float acc[4][8][4];        // [mt][nt][frag] -- warp tile 64x64
    uint32_t ar[2][4][4];      // A frags, double buffered
    uint32_t br[2][8][2];      // B frags, double buffered

    // issue both chunks of a pair as ONE commit group
    auto issue_pair = [&](int gp) {
        int nt = gp / PAIRS, pr = gp % PAIRS;
        int n0 = nt * BN;
        #pragma unroll
        for (int h = 0; h < 2; h++) {
            int c  = pr * 2 + h;                 // chunk within nt (0..23)
            uint32_t sb = smb + (uint32_t)(c & 3) * STAGE_B;
            // A: 2 kb x 128 rows x 32B = 8KB -> 512 x 16B, 2 per thread
            #pragma unroll
            for (int i = 0; i < 2; i++) {
                int o = tid + 256 * i, j = o >> 8, u = o & 255;
                const __half* src = g_za + ((size_t)(2 * c + j) * N_TOK + m0) * 16 + u * 8;
                cpasync16(sb + j * 4096 + u * 16, src);
            }
            // B: 2 kb x 256 rows x 32B = 16KB -> 1024 x 16B, 4 per thread
            #pragma unroll
            for (int i = 0; i < 4; i++) {
                int o = tid + 256 * i, j = o >> 9, u = o & 511;
                const __half* src = g_eb + ((size_t)(2 * c + j) * N_E + n0) * 16 + u * 8;
                cpasync16(sb + 8192 + j * 8192 + u * 16, src);
            }
        }
        CP_COMMIT();
    };

    // load fragments of k16-block kb (0..3) of pair pr into buffer bf
    auto load_frags = [&](int pr, int kb, int bf) {
        int c = pr * 2 + (kb >> 1);
        int b = kb & 1;
        const uint32_t Sb = (uint32_t)(c & 3) * STAGE_B;
        #pragma unroll
        for (int t = 0; t < 4; t++) {
            const char* ra = smc + Sb + b * 4096
                           + (wm * 64 + t * 16 + g) * 32 + tig * 8;
            uint2 v0 = *(const uint2*)ra;          // row g   : a0, a2
            uint2 v1 = *(const uint2*)(ra + 256);  // row g+8 : a1, a3
            ar[bf][t][0] = v0.x; ar[bf][t][2] = v0.y;
            ar[bf][t][1] = v1.x; ar[bf][t][3] = v1.y;
        }
        #pragma unroll
        for (int tn = 0; tn < 8; tn++) {
            const char* rb = smc + Sb + 8192 + b * 8192
                           + (wn * 64 + tn * 8 + g) * 32 + tig * 8;
            uint2 v = *(const uint2*)rb;
            br[bf][tn][0] = v.x; br[bf][tn][1] = v.y;
        }
    };

    issue_pair(0);

    for (int nt = 0; nt < NT; nt++) {
        #pragma unroll
        for (int t = 0; t < 4; t++)
            #pragma unroll
            for (int tn = 0; tn < 8; tn++)
                #pragma unroll
                for (int r = 0; r < 4; r++) acc[t][tn][r] = 0.f;

        for (int pr = 0; pr < PAIRS; pr++) {
            int gp = nt * PAIRS + pr;
            CP_WAIT(0);
            __syncthreads();
            if (gp + 1 < TOTAL_PR) issue_pair(gp + 1);

            load_frags(pr, 0, 0);
            #pragma unroll
            for (int kb = 0; kb < 4; kb++) {
                if (kb < 3) load_frags(pr, kb + 1, (kb + 1) & 1);
                const int bf = kb & 1;
                #pragma unroll
                for (int t = 0; t < 4; t++)
                    #pragma unroll
                    for (int tn = 0; tn < 8; tn++)
                        MMA_FP16(acc[t][tn],
                                 ar[bf][t][0], ar[bf][t][1], ar[bf][t][2], ar[bf][t][3],
                                 br[bf][tn][0], br[bf][tn][1]);
            }
        }

        // per-tile argmin fold; dot = acc * 2^-12, so s = fmaf(-2^-11, acc, zn+en)
        int n0 = nt * BN;
        #pragma unroll
        for (int t = 0; t < 4; t++) {
            #pragma unroll
            for (int tn = 0; tn < 8; tn++) {
                int cb = n0 + wn * 64 + tn * 8 + 2 * tig;
                float en0 = __ldg(&g_enorm[cb]);
                float en1 = __ldg(&g_enorm[cb + 1]);
                const float SC = -4.8828125e-4f;   // -2^-11, exact
                float s00 = fmaf(SC, acc[t][tn][0], zn[t][0] + en0);
                float s01 = fmaf(SC, acc[t][tn][1], zn[t][0] + en1);
                float s10 = fmaf(SC, acc[t][tn][2], zn[t][1] + en0);
                float s11 = fmaf(SC, acc[t][tn][3], zn[t][1] + en1);
                int s0 = t * 2, s1 = t * 2 + 1;
                if (s00 < best[s0]) { best[s0] = s00; bidx[s0] = cb; }
                if (s01 < best[s0]) { best[s0] = s01; bidx[s0] = cb + 1; }
                if (s10 < best[s1]) { best[s1] = s10; bidx[s1] = cb; }
                if (s11 < best[s1]) { best[s1] = s11; bidx[s1] = cb + 1; }
            }
        }
    }

    // merge across threads via packed (score,idx) atomicMin in smem
    __syncthreads();
    unsigned long long* sKey = (unsigned long long*)smc;
    if (tid < BM) sKey[tid] = 0xFFFFFFFFFFFFFFFFull;
    __syncthreads();
    #pragma unroll
    for (int slot = 0; slot < 8; slot++) {
        int t = slot >> 1, which = slot & 1;
        int rl = wm * 64 + t * 16 + g + which * 8;
        unsigned long long key =
            ((unsigned long long)f2o(best[slot]) << 32) | (unsigned)bidx[slot];
        atomicMin(&sKey[rl], key);
    }
    __syncthreads();
    if (tid < BM) {
        int idx = (int)(unsigned)(sKey[tid] & 0xFFFFFFFFull);
        g_idx[m0 + tid] = idx;
        out_idx_f[m0 + tid] = (float)idx;
    }
}

// ---------------- K3: gather z_q (straight-through rounding) + loss ------
__global__ void epilogue_kernel(const float* __restrict__ emb, float* __restrict__ out) {
    int bh = blockIdx.x;
    int b = bh >> 5, h = bh & 31;
    int w    = threadIdx.x >> 5;
    int lane = threadIdx.x & 31;
    int n = (b << 10) + (h << 5) + w;
    int idx = g_idx[n];

    const float4* ep = (const float4*)(emb  + idx * 256);
    const float4* zp = (const float4*)(g_zt + n   * 256);
    float ls = 0.f;
    #pragma unroll
    for (int i = 0; i < 2; i++) {
        float4 e  = ep[lane + 32 * i];
        float4 zv = zp[lane + 32 * i];
        int c = (lane + 32 * i) * 4;
        int base = (b * 256 + c) * 1024 + h * 32 + w;
        out[base]        = __fadd_rn(zv.x, __fsub_rn(e.x, zv.x));
        out[base + 1024] = __fadd_rn(zv.y, __fsub_rn(e.y, zv.y));
        out[base + 2048] = __fadd_rn(zv.z, __fsub_rn(e.z, zv.z));
        out[base + 3072] = __fadd_rn(zv.w, __fsub_rn(e.w, zv.w));
        float dx = e.x - zv.x, dy = e.y - zv.y, dz = e.z - zv.z, dw = e.w - zv.w;
        ls += dx * dx + dy * dy + dz * dz + dw * dw;
    }
    #pragma unroll
    for (int o = 16; o; o >>= 1) ls += __shfl_xor_sync(0xFFFFFFFFu, ls, o);
    __shared__ float red[32];
    if (lane == 0) red[w] = ls;
    __syncthreads();
    if (threadIdx.x < 32) {
        float v = red[threadIdx.x];
        #pragma unroll
        for (int o = 16; o; o >>= 1) v += __shfl_xor_sync(0xFFFFFFFFu, v, o);
        if (threadIdx.x == 0) atomicAdd(&g_loss, v);
    }
}

__global__ void finalize_kernel(float* __restrict__ out_loss) {
    out_loss[0] = 1.25f * g_loss * (1.0f / (float)ZQ_ELEMS);
}

// ---------------- launch ----------------
extern "C" void kernel_launch(void* const* d_in, const int* in_sizes, int n_in,
                              void* d_out, int out_size) {
    const float* z   = (const float*)d_in[0];
    const float* emb = (const float*)d_in[1];
    float* out = (float*)d_out;

    cudaFuncSetAttribute(vq_mma_kernel, cudaFuncAttributeMaxDynamicSharedMemorySize, SMEM_DYN);

    transpose_kernel<<<dim3(32, 8, 16), dim3(32, 8)>>>(z);
    embsplit_kernel<<<(N_E * E_DIM) / 256, 256>>>(emb);
    norms_kernel<<<(N_TOK + N_E) / 8, 256>>>(emb);
    vq_mma_kernel<<<N_TOK / BM, 256, SMEM_DYN>>>(out + ZQ_ELEMS + 1);
    epilogue_kernel<<<512, 1024>>>(emb, out);
    finalize_kernel<<<1, 1>>>(out + ZQ_ELEMS);
}